// round 14
// baseline (speedup 1.0000x reference)
#include <cuda_runtime.h>
#include <cuda_fp16.h>
#include <cstdint>

#define NB 32
#define NS 8
#define NT 512
#define NC 128
#define NH 128

// Scratch (allocation-free rule: module-scope device arrays)
static __device__ __align__(16) __half g_q[(size_t)NB * NT * NH];
static __device__ __align__(16) __half g_k[(size_t)NB * NT * NH];
static __device__ __align__(16) __half g_v[(size_t)NB * NT * NH];
static __device__ __align__(16) __half g_s[(size_t)NB * NT * NT];   // fp16 scores

__device__ __forceinline__ uint32_t smem_u32(const void* p) {
    return (uint32_t)__cvta_generic_to_shared(p);
}

__device__ __forceinline__ void ldm_x4(uint32_t& r0, uint32_t& r1, uint32_t& r2, uint32_t& r3, uint32_t addr) {
    asm volatile("ldmatrix.sync.aligned.m8n8.x4.shared.b16 {%0,%1,%2,%3}, [%4];"
                 : "=r"(r0), "=r"(r1), "=r"(r2), "=r"(r3) : "r"(addr));
}
__device__ __forceinline__ void ldm_x2(uint32_t& r0, uint32_t& r1, uint32_t addr) {
    asm volatile("ldmatrix.sync.aligned.m8n8.x2.shared.b16 {%0,%1}, [%2];"
                 : "=r"(r0), "=r"(r1) : "r"(addr));
}
__device__ __forceinline__ void ldm_x2_trans(uint32_t& r0, uint32_t& r1, uint32_t addr) {
    asm volatile("ldmatrix.sync.aligned.m8n8.x2.trans.shared.b16 {%0,%1}, [%2];"
                 : "=r"(r0), "=r"(r1) : "r"(addr));
}
__device__ __forceinline__ void mma_16816(float& d0, float& d1, float& d2, float& d3,
                                          uint32_t a0, uint32_t a1, uint32_t a2, uint32_t a3,
                                          uint32_t b0, uint32_t b1) {
    asm volatile("mma.sync.aligned.m16n8k16.row.col.f32.f16.f16.f32 "
                 "{%0,%1,%2,%3}, {%4,%5,%6,%7}, {%8,%9}, {%0,%1,%2,%3};"
                 : "+f"(d0), "+f"(d1), "+f"(d2), "+f"(d3)
                 : "r"(a0), "r"(a1), "r"(a2), "r"(a3), "r"(b0), "r"(b1));
}
__device__ __forceinline__ void cp16(uint32_t smem_addr, const void* gptr) {
    asm volatile("cp.async.cg.shared.global [%0], [%1], 16;" :: "r"(smem_addr), "l"(gptr));
}
__device__ __forceinline__ void cp_commit() { asm volatile("cp.async.commit_group;"); }
template <int N>
__device__ __forceinline__ void cp_wait() { asm volatile("cp.async.wait_group %0;" :: "n"(N)); }

// ---------------------------------------------------------------------------
// Kernel 1: fused QKV.  grid = NB*NT/64 = 256, block = 256.
// x tile read ONCE; loop over 3 W's x 2 k-halves with W-register prefetch
// overlapping the MMA of the previous phase.
// ---------------------------------------------------------------------------
__global__ void __launch_bounds__(256) qkv_kernel(const float* __restrict__ x,
                                                  const float* __restrict__ Wq,
                                                  const float* __restrict__ Wk,
                                                  const float* __restrict__ Wv) {
    __shared__ __half sx[64][136];   // x tile fp16 (persistent)
    __shared__ __half sw[64][136];   // W half-tile fp16 (per phase)

    const int tid = threadIdx.x, lane = tid & 31, w = tid >> 5;
    const int row0 = blockIdx.x * 64;
    const float* Ws[3] = {Wq, Wk, Wv};
    __half* outs[3]    = {g_q, g_k, g_v};

    // x tile: 64 rows x 128 f32 -> fp16 smem
    #pragma unroll
    for (int i = 0; i < 8; i++) {
        int f = tid + i * 256;
        int r = f >> 5, c4 = f & 31;
        float4 v4 = *(const float4*)(x + (size_t)(row0 + r) * NC + c4 * 4);
        __half2* dst = (__half2*)&sx[r][c4 * 4];
        dst[0] = __floats2half2_rn(v4.x, v4.y);
        dst[1] = __floats2half2_rn(v4.z, v4.w);
    }

    const int ldr = tid >> 5, ldc4 = tid & 31;   // W load mapping (8 rows/pass)
    // preload phase 0 W regs (Wq, kh=0)
    float4 wreg[8];
    #pragma unroll
    for (int i = 0; i < 8; i++)
        wreg[i] = *(const float4*)(Ws[0] + (size_t)(0 * 64 + ldr + i * 8) * NH + ldc4 * 4);

    const int tblk = (w >> 1) * 16, hsb = (w & 1) * 64;
    float acc[8][4];
    #pragma unroll
    for (int j = 0; j < 8; j++)
        #pragma unroll
        for (int q = 0; q < 4; q++) acc[j][q] = 0.f;

    for (int p = 0; p < 6; p++) {
        const int kh = p & 1;
        // store W regs -> sw (fp16)
        #pragma unroll
        for (int i = 0; i < 8; i++) {
            __half2* dst = (__half2*)&sw[ldr + i * 8][ldc4 * 4];
            dst[0] = __floats2half2_rn(wreg[i].x, wreg[i].y);
            dst[1] = __floats2half2_rn(wreg[i].z, wreg[i].w);
        }
        __syncthreads();   // sw (and, on p==0, sx) visible

        // preload next phase W regs (overlaps MMA)
        if (p < 5) {
            const int pn = p + 1, wsel = pn >> 1, khn = pn & 1;
            #pragma unroll
            for (int i = 0; i < 8; i++)
                wreg[i] = *(const float4*)(Ws[wsel] + (size_t)(khn * 64 + ldr + i * 8) * NH + ldc4 * 4);
        }

        // acc += sx[:, kh*64 : kh*64+64] @ sw
        #pragma unroll
        for (int kk = 0; kk < 4; kk++) {
            uint32_t a0, a1, a2, a3;
            ldm_x4(a0, a1, a2, a3,
                   smem_u32(&sx[tblk + (lane & 15)][(kh * 4 + kk) * 16 + ((lane >> 4) << 3)]));
            #pragma unroll
            for (int j = 0; j < 8; j++) {
                uint32_t b0, b1;
                ldm_x2_trans(b0, b1, smem_u32(&sw[kk * 16 + (lane & 15)][hsb + j * 8]));
                mma_16816(acc[j][0], acc[j][1], acc[j][2], acc[j][3], a0, a1, a2, a3, b0, b1);
            }
        }
        __syncthreads();   // all MMA reads of sw done before next overwrite

        if (kh == 1) {
            __half* outp = outs[p >> 1];
            const int g = lane >> 2, c2 = (lane & 3) * 2;
            #pragma unroll
            for (int j = 0; j < 8; j++) {
                *(__half2*)&outp[(size_t)(row0 + tblk + g) * NH + hsb + j * 8 + c2] =
                    __floats2half2_rn(acc[j][0], acc[j][1]);
                *(__half2*)&outp[(size_t)(row0 + tblk + 8 + g) * NH + hsb + j * 8 + c2] =
                    __floats2half2_rn(acc[j][2], acc[j][3]);
                #pragma unroll
                for (int q = 0; q < 4; q++) acc[j][q] = 0.f;
            }
        }
    }
}

// ---------------------------------------------------------------------------
// Kernel 2: scores[b,t,u] = (q[b,t] . k[b,u]) * C^-0.5  -> fp16
// grid = (NT/64, NT/64, NB), block = 256.
// ---------------------------------------------------------------------------
__global__ void __launch_bounds__(256) scores_kernel() {
    __shared__ __half sq_[64][136];
    __shared__ __half sk_[64][136];
    const int tid = threadIdx.x, lane = tid & 31, w = tid >> 5;
    const int t0 = blockIdx.x * 64, u0 = blockIdx.y * 64, b = blockIdx.z;

    const __half* qb = g_q + (size_t)b * NT * NH;
    const __half* kb = g_k + (size_t)b * NT * NH;
    #pragma unroll
    for (int i = 0; i < 4; i++) {
        int f = tid + i * 256;
        int r = f >> 4, c8 = (f & 15) * 8;
        *(uint4*)&sq_[r][c8] = *(const uint4*)(qb + (size_t)(t0 + r) * NH + c8);
        *(uint4*)&sk_[r][c8] = *(const uint4*)(kb + (size_t)(u0 + r) * NH + c8);
    }
    __syncthreads();

    const int tblk = (w >> 1) * 16, ub = (w & 1) * 32;
    float acc[4][4];
    #pragma unroll
    for (int j = 0; j < 4; j++)
        #pragma unroll
        for (int q = 0; q < 4; q++) acc[j][q] = 0.f;

    #pragma unroll
    for (int kk = 0; kk < 8; kk++) {
        uint32_t a0, a1, a2, a3;
        ldm_x4(a0, a1, a2, a3,
               smem_u32(&sq_[tblk + (lane & 15)][kk * 16 + ((lane >> 4) << 3)]));
        #pragma unroll
        for (int j = 0; j < 4; j++) {
            uint32_t b0, b1;
            ldm_x2(b0, b1, smem_u32(&sk_[ub + j * 8 + (lane & 7)][kk * 16 + ((lane >> 3) & 1) * 8]));
            mma_16816(acc[j][0], acc[j][1], acc[j][2], acc[j][3], a0, a1, a2, a3, b0, b1);
        }
    }

    const float sc = 0.08838834764831845f;  // 128^-0.5
    const int g = lane >> 2, c2 = (lane & 3) * 2;
    __half* srow = g_s + (size_t)b * NT * NT;
    #pragma unroll
    for (int j = 0; j < 4; j++) {
        *(__half2*)&srow[(size_t)(t0 + tblk + g) * NT + u0 + ub + j * 8 + c2] =
            __floats2half2_rn(acc[j][0] * sc, acc[j][1] * sc);
        *(__half2*)&srow[(size_t)(t0 + tblk + 8 + g) * NT + u0 + ub + j * 8 + c2] =
            __floats2half2_rn(acc[j][2] * sc, acc[j][3] * sc);
    }
}

// ---------------------------------------------------------------------------
// Kernel 3: attention.  grid = (NT/64, NS, NB), block = 256, dynamic smem.
// adj (fp32) + scores (fp16) staged through smem via cp.async, 2 stages,
// PER-THREAD-PRIVATE chunks (no barriers for staging; per-thread wait_group).
// Group commit order per thread: S0,V0, S1,V1, ... (S = adj+score stage,
// V = v tile; empty groups committed at the tail to keep counts uniform).
//   exp(it) needs S(it):  wait_group 2  (pending allowed: S(it+1), V(it))
//   MMA(it) needs V(it):  wait_group 1  (pending allowed: S(it+1))
// Stage smem layout is slice-interleaved so warp LDS.128 is conflict-free:
//   16B slice i of thread tid lives at [i*256 + tid].
// ---------------------------------------------------------------------------
#define ATTN_SMEM_BYTES (32768 + 16384 + 17408 + 9216 + 256)   // 76032

__global__ void __launch_bounds__(256) attn_kernel(const float* __restrict__ adj,
                                                   float* __restrict__ outp) {
    extern __shared__ __align__(16) unsigned char dynsmem[];
    float4* abuf = (float4*)(dynsmem);                       // [2][1024] adj fp32
    uint4*  scb  = (uint4*)(dynsmem + 32768);                // [2][512]  score fp16
    __half (*sv)[136] = (__half(*)[136])(dynsmem + 49152);   // v tile
    __half (*sp)[72]  = (__half(*)[72])(dynsmem + 66560);    // p tile
    float*  sl = (float*)(dynsmem + 75776);                  // row sums

    const int tid = threadIdx.x, lane = tid & 31, w = tid >> 5;
    const int t0 = blockIdx.x * 64, s = blockIdx.y, b = blockIdx.z;

    const float*  adj_base = adj + ((size_t)(b * NS + s) * NT + t0) * NT;
    const __half* sc_base  = g_s + ((size_t)b * NT + t0) * NT;
    const __half* vb       = g_v + (size_t)b * NT * NH;

    if (tid < 64) sl[tid] = 0.f;

    const int r = tid >> 2, cqb = (tid & 3) * 16;     // this thread's 16-elem row segment
    const int tblk = (w >> 1) * 16, hsb = (w & 1) * 64;

    const float*  arow = adj_base + (size_t)r * NT + cqb;
    const __half* srow = sc_base + (size_t)r * NT + cqb;

    // v-tile cp.async mapping: 4 x 16B per thread
    const int vr = tid >> 4, vc = (tid & 15) * 8;

    float acc[8][4];
    #pragma unroll
    for (int j = 0; j < 8; j++)
        #pragma unroll
        for (int q = 0; q < 4; q++) acc[j][q] = 0.f;

    // ---- prologue: stage S(0), then V(0) ----
    {
        uint32_t a_s = smem_u32(&abuf[tid]);            // buf 0: [i*256 + tid]
        uint32_t s_s = smem_u32(&scb[tid]);
        #pragma unroll
        for (int i = 0; i < 4; i++) cp16(a_s + i * 256 * 16, arow + i * 4);
        #pragma unroll
        for (int i = 0; i < 2; i++) cp16(s_s + i * 256 * 16, srow + i * 8);
        cp_commit();   // S(0)
        #pragma unroll
        for (int i = 0; i < 4; i++)
            cp16(smem_u32(&sv[vr + i * 16][vc]), vb + (size_t)(vr + i * 16) * NH + vc);
        cp_commit();   // V(0)
    }
    __syncthreads();   // sl init visible before first accumulation

    for (int it = 0; it < 8; it++) {
        const int buf = it & 1, nbuf = buf ^ 1;

        // ---- issue S(it+1) (possibly empty group at it==7) ----
        if (it < 7) {
            const float*  an = arow + (it + 1) * 64;
            const __half* sn = srow + (it + 1) * 64;
            uint32_t a_s = smem_u32(&abuf[nbuf * 1024 + tid]);
            uint32_t s_s = smem_u32(&scb[nbuf * 512 + tid]);
            #pragma unroll
            for (int i = 0; i < 4; i++) cp16(a_s + i * 256 * 16, an + i * 4);
            #pragma unroll
            for (int i = 0; i < 2; i++) cp16(s_s + i * 256 * 16, sn + i * 8);
        }
        cp_commit();   // S(it+1)

        cp_wait<2>();  // S(it) resident (pending: S(it+1), V(it))

        // ---- p = exp(adj * score) from staged smem ----
        float af[16], sf[16];
        #pragma unroll
        for (int i = 0; i < 4; i++) {
            float4 a4 = abuf[buf * 1024 + i * 256 + tid];
            af[i * 4 + 0] = a4.x; af[i * 4 + 1] = a4.y;
            af[i * 4 + 2] = a4.z; af[i * 4 + 3] = a4.w;
        }
        #pragma unroll
        for (int i = 0; i < 2; i++) {
            uint4 su = scb[buf * 512 + i * 256 + tid];
            const __half2* h2 = (const __half2*)&su;
            #pragma unroll
            for (int q = 0; q < 4; q++) {
                float2 f2 = __half22float2(h2[q]);
                sf[i * 8 + q * 2]     = f2.x;
                sf[i * 8 + q * 2 + 1] = f2.y;
            }
        }
        float psum = 0.f;
        __align__(16) __half2 ph[8];
        #pragma unroll
        for (int e = 0; e < 8; e++) {
            float p0 = __expf(af[e * 2] * sf[e * 2]);
            float p1 = __expf(af[e * 2 + 1] * sf[e * 2 + 1]);
            psum += p0 + p1;
            ph[e] = __floats2half2_rn(p0, p1);
        }
        *(uint4*)&sp[r][cqb]     = *(uint4*)&ph[0];
        *(uint4*)&sp[r][cqb + 8] = *(uint4*)&ph[4];

        psum += __shfl_xor_sync(0xffffffffu, psum, 1);
        psum += __shfl_xor_sync(0xffffffffu, psum, 2);
        if ((tid & 3) == 0) sl[r] += psum;   // unique writer per row

        cp_wait<1>();      // V(it) resident (pending: S(it+1))
        __syncthreads();   // BAR1: sp + sv ready for all

        // ---- acc += p[64,64] @ v[64,128] ----
        #pragma unroll
        for (int kk = 0; kk < 4; kk++) {
            uint32_t a0, a1, a2, a3;
            ldm_x4(a0, a1, a2, a3,
                   smem_u32(&sp[tblk + (lane & 15)][kk * 16 + ((lane >> 4) << 3)]));
            #pragma unroll
            for (int j = 0; j < 8; j++) {
                uint32_t b0, b1;
                ldm_x2_trans(b0, b1, smem_u32(&sv[kk * 16 + (lane & 15)][hsb + j * 8]));
                mma_16816(acc[j][0], acc[j][1], acc[j][2], acc[j][3], a0, a1, a2, a3, b0, b1);
            }
        }
        __syncthreads();   // BAR2: all MMA reads of sp/sv complete

        // ---- issue V(it+1) (possibly empty group at it==7) ----
        if (it < 7) {
            const __half* vn = vb + (size_t)(it + 1) * 64 * NH;
            #pragma unroll
            for (int i = 0; i < 4; i++)
                cp16(smem_u32(&sv[vr + i * 16][vc]), vn + (size_t)(vr + i * 16) * NH + vc);
        }
        cp_commit();   // V(it+1)
    }

    const int g = lane >> 2, c2 = (lane & 3) * 2;
    const float il0 = 1.f / sl[tblk + g];
    const float il1 = 1.f / sl[tblk + 8 + g];
    float* ob = outp + ((size_t)(b * NS + s) * NT + t0) * NH;
    #pragma unroll
    for (int j = 0; j < 8; j++) {
        *(float2*)&ob[(size_t)(tblk + g) * NH + hsb + j * 8 + c2] =
            make_float2(acc[j][0] * il0, acc[j][1] * il0);
        *(float2*)&ob[(size_t)(tblk + 8 + g) * NH + hsb + j * 8 + c2] =
            make_float2(acc[j][2] * il1, acc[j][3] * il1);
    }
}

// ---------------------------------------------------------------------------
extern "C" void kernel_launch(void* const* d_in, const int* in_sizes, int n_in,
                              void* d_out, int out_size) {
    (void)in_sizes; (void)n_in; (void)out_size;
    const float* x   = (const float*)d_in[0];
    const float* adj = (const float*)d_in[1];
    const float* Wq  = (const float*)d_in[2];
    const float* Wk  = (const float*)d_in[3];
    const float* Wv  = (const float*)d_in[4];
    float* out = (float*)d_out;

    // Host-side attribute set: idempotent, not a stream op (not captured),
    // called unconditionally — no static guards per harness rules.
    cudaFuncSetAttribute(attn_kernel, cudaFuncAttributeMaxDynamicSharedMemorySize,
                         ATTN_SMEM_BYTES);

    qkv_kernel<<<dim3(NB * NT / 64, 1, 1), 256>>>(x, Wq, Wk, Wv);
    scores_kernel<<<dim3(NT / 64, NT / 64, NB), 256>>>();
    attn_kernel<<<dim3(NT / 64, NS, NB), 256, ATTN_SMEM_BYTES>>>(adj, out);
}

// round 16
// speedup vs baseline: 1.0946x; 1.0946x over previous
#include <cuda_runtime.h>
#include <cuda_fp16.h>
#include <cstdint>

#define NB 32
#define NS 8
#define NT 512
#define NC 128
#define NH 128

// Scratch (allocation-free rule: module-scope device arrays)
static __device__ __align__(16) __half g_q[(size_t)NB * NT * NH];
static __device__ __align__(16) __half g_k[(size_t)NB * NT * NH];
static __device__ __align__(16) __half g_v[(size_t)NB * NT * NH];
static __device__ __align__(16) __half g_s[(size_t)NB * NT * NT];   // fp16 scores

__device__ __forceinline__ uint32_t smem_u32(const void* p) {
    return (uint32_t)__cvta_generic_to_shared(p);
}

__device__ __forceinline__ void ldm_x4(uint32_t& r0, uint32_t& r1, uint32_t& r2, uint32_t& r3, uint32_t addr) {
    asm volatile("ldmatrix.sync.aligned.m8n8.x4.shared.b16 {%0,%1,%2,%3}, [%4];"
                 : "=r"(r0), "=r"(r1), "=r"(r2), "=r"(r3) : "r"(addr));
}
__device__ __forceinline__ void ldm_x2(uint32_t& r0, uint32_t& r1, uint32_t addr) {
    asm volatile("ldmatrix.sync.aligned.m8n8.x2.shared.b16 {%0,%1}, [%2];"
                 : "=r"(r0), "=r"(r1) : "r"(addr));
}
__device__ __forceinline__ void ldm_x2_trans(uint32_t& r0, uint32_t& r1, uint32_t addr) {
    asm volatile("ldmatrix.sync.aligned.m8n8.x2.trans.shared.b16 {%0,%1}, [%2];"
                 : "=r"(r0), "=r"(r1) : "r"(addr));
}
__device__ __forceinline__ void ldm_x4_trans(uint32_t& r0, uint32_t& r1, uint32_t& r2, uint32_t& r3, uint32_t addr) {
    asm volatile("ldmatrix.sync.aligned.m8n8.x4.trans.shared.b16 {%0,%1,%2,%3}, [%4];"
                 : "=r"(r0), "=r"(r1), "=r"(r2), "=r"(r3) : "r"(addr));
}
__device__ __forceinline__ void mma_16816(float& d0, float& d1, float& d2, float& d3,
                                          uint32_t a0, uint32_t a1, uint32_t a2, uint32_t a3,
                                          uint32_t b0, uint32_t b1) {
    asm volatile("mma.sync.aligned.m16n8k16.row.col.f32.f16.f16.f32 "
                 "{%0,%1,%2,%3}, {%4,%5,%6,%7}, {%8,%9}, {%0,%1,%2,%3};"
                 : "+f"(d0), "+f"(d1), "+f"(d2), "+f"(d3)
                 : "r"(a0), "r"(a1), "r"(a2), "r"(a3), "r"(b0), "r"(b1));
}
__device__ __forceinline__ void cp16(uint32_t smem_addr, const void* gptr) {
    asm volatile("cp.async.cg.shared.global [%0], [%1], 16;" :: "r"(smem_addr), "l"(gptr));
}
__device__ __forceinline__ void cp_commit() { asm volatile("cp.async.commit_group;"); }
template <int N>
__device__ __forceinline__ void cp_wait() { asm volatile("cp.async.wait_group %0;" :: "n"(N)); }

// ---------------------------------------------------------------------------
// Kernel 1: fused QKV (unchanged; 17.0us measured, not the lever this round).
// ---------------------------------------------------------------------------
__global__ void __launch_bounds__(256) qkv_kernel(const float* __restrict__ x,
                                                  const float* __restrict__ Wq,
                                                  const float* __restrict__ Wk,
                                                  const float* __restrict__ Wv) {
    __shared__ __half sx[64][136];
    __shared__ __half sw[64][136];

    const int tid = threadIdx.x, lane = tid & 31, w = tid >> 5;
    const int row0 = blockIdx.x * 64;
    const float* Ws[3] = {Wq, Wk, Wv};
    __half* outs[3]    = {g_q, g_k, g_v};

    #pragma unroll
    for (int i = 0; i < 8; i++) {
        int f = tid + i * 256;
        int r = f >> 5, c4 = f & 31;
        float4 v4 = *(const float4*)(x + (size_t)(row0 + r) * NC + c4 * 4);
        __half2* dst = (__half2*)&sx[r][c4 * 4];
        dst[0] = __floats2half2_rn(v4.x, v4.y);
        dst[1] = __floats2half2_rn(v4.z, v4.w);
    }

    const int ldr = tid >> 5, ldc4 = tid & 31;
    float4 wreg[8];
    #pragma unroll
    for (int i = 0; i < 8; i++)
        wreg[i] = *(const float4*)(Ws[0] + (size_t)(ldr + i * 8) * NH + ldc4 * 4);

    const int tblk = (w >> 1) * 16, hsb = (w & 1) * 64;
    float acc[8][4];
    #pragma unroll
    for (int j = 0; j < 8; j++)
        #pragma unroll
        for (int q = 0; q < 4; q++) acc[j][q] = 0.f;

    for (int p = 0; p < 6; p++) {
        const int kh = p & 1;
        #pragma unroll
        for (int i = 0; i < 8; i++) {
            __half2* dst = (__half2*)&sw[ldr + i * 8][ldc4 * 4];
            dst[0] = __floats2half2_rn(wreg[i].x, wreg[i].y);
            dst[1] = __floats2half2_rn(wreg[i].z, wreg[i].w);
        }
        __syncthreads();

        if (p < 5) {
            const int pn = p + 1, wsel = pn >> 1, khn = pn & 1;
            #pragma unroll
            for (int i = 0; i < 8; i++)
                wreg[i] = *(const float4*)(Ws[wsel] + (size_t)(khn * 64 + ldr + i * 8) * NH + ldc4 * 4);
        }

        #pragma unroll
        for (int kk = 0; kk < 4; kk++) {
            uint32_t a0, a1, a2, a3;
            ldm_x4(a0, a1, a2, a3,
                   smem_u32(&sx[tblk + (lane & 15)][(kh * 4 + kk) * 16 + ((lane >> 4) << 3)]));
            #pragma unroll
            for (int j = 0; j < 8; j++) {
                uint32_t b0, b1;
                ldm_x2_trans(b0, b1, smem_u32(&sw[kk * 16 + (lane & 15)][hsb + j * 8]));
                mma_16816(acc[j][0], acc[j][1], acc[j][2], acc[j][3], a0, a1, a2, a3, b0, b1);
            }
        }
        __syncthreads();

        if (kh == 1) {
            __half* outp = outs[p >> 1];
            const int g = lane >> 2, c2 = (lane & 3) * 2;
            #pragma unroll
            for (int j = 0; j < 8; j++) {
                *(__half2*)&outp[(size_t)(row0 + tblk + g) * NH + hsb + j * 8 + c2] =
                    __floats2half2_rn(acc[j][0], acc[j][1]);
                *(__half2*)&outp[(size_t)(row0 + tblk + 8 + g) * NH + hsb + j * 8 + c2] =
                    __floats2half2_rn(acc[j][2], acc[j][3]);
                #pragma unroll
                for (int q = 0; q < 4; q++) acc[j][q] = 0.f;
            }
        }
    }
}

// ---------------------------------------------------------------------------
// Kernel 2: scores -> fp16 (unchanged).
// ---------------------------------------------------------------------------
__global__ void __launch_bounds__(256) scores_kernel() {
    __shared__ __half sq_[64][136];
    __shared__ __half sk_[64][136];
    const int tid = threadIdx.x, lane = tid & 31, w = tid >> 5;
    const int t0 = blockIdx.x * 64, u0 = blockIdx.y * 64, b = blockIdx.z;

    const __half* qb = g_q + (size_t)b * NT * NH;
    const __half* kb = g_k + (size_t)b * NT * NH;
    #pragma unroll
    for (int i = 0; i < 4; i++) {
        int f = tid + i * 256;
        int r = f >> 4, c8 = (f & 15) * 8;
        *(uint4*)&sq_[r][c8] = *(const uint4*)(qb + (size_t)(t0 + r) * NH + c8);
        *(uint4*)&sk_[r][c8] = *(const uint4*)(kb + (size_t)(u0 + r) * NH + c8);
    }
    __syncthreads();

    const int tblk = (w >> 1) * 16, ub = (w & 1) * 32;
    float acc[4][4];
    #pragma unroll
    for (int j = 0; j < 4; j++)
        #pragma unroll
        for (int q = 0; q < 4; q++) acc[j][q] = 0.f;

    #pragma unroll
    for (int kk = 0; kk < 8; kk++) {
        uint32_t a0, a1, a2, a3;
        ldm_x4(a0, a1, a2, a3,
               smem_u32(&sq_[tblk + (lane & 15)][kk * 16 + ((lane >> 4) << 3)]));
        #pragma unroll
        for (int j = 0; j < 4; j++) {
            uint32_t b0, b1;
            ldm_x2(b0, b1, smem_u32(&sk_[ub + j * 8 + (lane & 7)][kk * 16 + ((lane >> 3) & 1) * 8]));
            mma_16816(acc[j][0], acc[j][1], acc[j][2], acc[j][3], a0, a1, a2, a3, b0, b1);
        }
    }

    const float sc = 0.08838834764831845f;  // 128^-0.5
    const int g = lane >> 2, c2 = (lane & 3) * 2;
    __half* srow = g_s + (size_t)b * NT * NT;
    #pragma unroll
    for (int j = 0; j < 4; j++) {
        *(__half2*)&srow[(size_t)(t0 + tblk + g) * NT + u0 + ub + j * 8 + c2] =
            __floats2half2_rn(acc[j][0] * sc, acc[j][1] * sc);
        *(__half2*)&srow[(size_t)(t0 + tblk + 8 + g) * NT + u0 + ub + j * 8 + c2] =
            __floats2half2_rn(acc[j][2] * sc, acc[j][3] * sc);
    }
}

// ---------------------------------------------------------------------------
// Kernel 3: WARP-SPECIALIZED attention.  grid (NT/64, NS, NB), block 256.
// Warps 0-3 (softmax/producer): per iter, compute p(it+1)=exp(adj*score) into
//   sp[nbuf] (adj/score prefetched to regs one tile ahead), issue cp.async of
//   v tile it+1 into sv[nbuf], keep per-thread row-sum accumulators.
// Warps 4-7 (MMA/consumer): per iter, acc += p(it)[16x64] @ v(it)[64x128]
//   from sp[buf]/sv[buf] (warp m owns t-rows 16m..16m+15, all 128 hs cols).
// ONE __syncthreads per iteration swaps buffers; MUFU (producers) and HMMA
// (consumers) overlap inside each window instead of serializing.
// Buffer safety: sv[nbuf]/sp[nbuf] were last read by MMA(it-1), which finished
// at the previous barrier; producer cp_wait<0> before the barrier guarantees
// v(it+1) landed; the barrier publishes sp/sv to consumers.
// Row sums: thread-local (2 threads per row), merged once in epilogue.
// ---------------------------------------------------------------------------
#define ATTN_SMEM_BYTES (18432 + 34816 + 256)   // sp[2][64][72] + sv[2][64][136] + sl[64]

__global__ void __launch_bounds__(256) attn_kernel(const float* __restrict__ adj,
                                                   float* __restrict__ outp) {
    extern __shared__ __align__(16) unsigned char dynsmem[];
    __half (*sp)[72]  = (__half(*)[72])(dynsmem);            // [2*64][72]
    __half (*sv)[136] = (__half(*)[136])(dynsmem + 18432);   // [2*64][136]
    float*  sl = (float*)(dynsmem + 18432 + 34816);          // [64]

    const int tid = threadIdx.x, lane = tid & 31, w = tid >> 5;
    const int t0 = blockIdx.x * 64, s = blockIdx.y, b = blockIdx.z;

    const float*  adj_base = adj + ((size_t)(b * NS + s) * NT + t0) * NT;
    const __half* sc_base  = g_s + ((size_t)b * NT + t0) * NT;
    const __half* vb       = g_v + (size_t)b * NT * NH;

    if (w < 4) {
        // ---------------- producer warps ----------------
        const int row  = w * 16 + (lane >> 1);     // t-row owned (2 threads/row)
        const int col0 = (lane & 1) * 32;          // 32-col half owned
        const float*  ap = adj_base + (size_t)row * NT + col0;
        const __half* st = sc_base + (size_t)row * NT + col0;

        // v cp.async mapping: 128 producer threads x 8 x 16B = 64x128 fp16 tile
        // linear uint4 index q = i*128 + tid -> vrow = q>>4, vc8 = (q&15)*8
        float4 pa[8];                  // 32 adj fp32 (prefetched)
        uint4  ps[4];                  // 32 score fp16
        float  l_acc = 0.f;

        // prefetch S(0)
        #pragma unroll
        for (int i = 0; i < 8; i++) pa[i] = ((const float4*)ap)[i];
        #pragma unroll
        for (int i = 0; i < 4; i++) ps[i] = ((const uint4*)st)[i];

        // V(0) -> sv buffer 0
        #pragma unroll
        for (int i = 0; i < 8; i++) {
            int q = i * 128 + tid;
            int vrow = q >> 4, vc8 = (q & 15) * 8;
            cp16(smem_u32(&sv[vrow][vc8]), vb + (size_t)vrow * NH + vc8);
        }
        cp_commit();

        // compute p(0) -> sp buffer 0 ; prefetch S(1)
        {
            __align__(16) __half2 ph[16];
            #pragma unroll
            for (int e = 0; e < 16; e++) {
                const float a0f = ((const float*)pa)[e * 2];
                const float a1f = ((const float*)pa)[e * 2 + 1];
                const __half2 h2 = ((const __half2*)ps)[e];
                float2 f2 = __half22float2(h2);
                float p0 = __expf(a0f * f2.x);
                float p1 = __expf(a1f * f2.y);
                l_acc += p0 + p1;
                ph[e] = __floats2half2_rn(p0, p1);
            }
            #pragma unroll
            for (int k = 0; k < 4; k++)
                ((uint4*)&sp[row][col0])[k] = ((const uint4*)ph)[k];
        }
        #pragma unroll
        for (int i = 0; i < 8; i++) pa[i] = ((const float4*)(ap + 64))[i];
        #pragma unroll
        for (int i = 0; i < 4; i++) ps[i] = ((const uint4*)(st + 64))[i];

        cp_wait<0>();      // V(0) resident
        __syncthreads();   // publish sp[0], sv[0]

        for (int it = 0; it < 8; it++) {
            const int nbuf = (it & 1) ^ 1;
            if (it < 7) {
                // V(it+1) -> sv[nbuf]  (MMA(it-1) finished with it at last bar)
                const __half* vn = vb + (size_t)(it + 1) * 64 * NH;
                #pragma unroll
                for (int i = 0; i < 8; i++) {
                    int q = i * 128 + tid;
                    int vrow = q >> 4, vc8 = (q & 15) * 8;
                    cp16(smem_u32(&sv[nbuf * 64 + vrow][vc8]), vn + (size_t)vrow * NH + vc8);
                }
                cp_commit();

                // p(it+1) -> sp[nbuf]
                __align__(16) __half2 ph[16];
                #pragma unroll
                for (int e = 0; e < 16; e++) {
                    const float a0f = ((const float*)pa)[e * 2];
                    const float a1f = ((const float*)pa)[e * 2 + 1];
                    const __half2 h2 = ((const __half2*)ps)[e];
                    float2 f2 = __half22float2(h2);
                    float p0 = __expf(a0f * f2.x);
                    float p1 = __expf(a1f * f2.y);
                    l_acc += p0 + p1;
                    ph[e] = __floats2half2_rn(p0, p1);
                }
                #pragma unroll
                for (int k = 0; k < 4; k++)
                    ((uint4*)&sp[nbuf * 64 + row][col0])[k] = ((const uint4*)ph)[k];

                // prefetch S(it+2)
                if (it < 6) {
                    const float*  an = ap + (it + 2) * 64;
                    const __half* sn = st + (it + 2) * 64;
                    #pragma unroll
                    for (int i = 0; i < 8; i++) pa[i] = ((const float4*)an)[i];
                    #pragma unroll
                    for (int i = 0; i < 4; i++) ps[i] = ((const uint4*)sn)[i];
                }
                cp_wait<0>();   // V(it+1) resident
            }
            __syncthreads();    // swap buffers
        }

        // merge row sums (2 threads per row)
        float psum = l_acc + __shfl_xor_sync(0xffffffffu, l_acc, 1);
        if ((lane & 1) == 0) sl[row] = psum;
        __syncthreads();
    } else {
        // ---------------- consumer (MMA) warps ----------------
        const int m = w - 4;                 // t-row block 16m..16m+15
        float acc[16][4];
        #pragma unroll
        for (int j = 0; j < 16; j++)
            #pragma unroll
            for (int q = 0; q < 4; q++) acc[j][q] = 0.f;

        __syncthreads();   // matches producer prologue bar

        for (int it = 0; it < 8; it++) {
            const int buf = it & 1;
            #pragma unroll
            for (int kk = 0; kk < 4; kk++) {
                uint32_t a0, a1, a2, a3;
                ldm_x4(a0, a1, a2, a3,
                       smem_u32(&sp[buf * 64 + m * 16 + (lane & 15)][kk * 16 + ((lane >> 4) << 3)]));
                #pragma unroll
                for (int jj = 0; jj < 8; jj++) {
                    uint32_t b0, b1, b2, b3;
                    ldm_x4_trans(b0, b1, b2, b3,
                                 smem_u32(&sv[buf * 64 + kk * 16 + (lane & 15)][jj * 16 + ((lane >> 4) << 3)]));
                    mma_16816(acc[2 * jj][0], acc[2 * jj][1], acc[2 * jj][2], acc[2 * jj][3],
                              a0, a1, a2, a3, b0, b1);
                    mma_16816(acc[2 * jj + 1][0], acc[2 * jj + 1][1], acc[2 * jj + 1][2], acc[2 * jj + 1][3],
                              a0, a1, a2, a3, b2, b3);
                }
            }
            __syncthreads();   // done reading sp[buf], sv[buf]
        }
        __syncthreads();       // matches producer sl-publish bar

        const int g = lane >> 2, c2 = (lane & 3) * 2;
        const float il0 = 1.f / sl[m * 16 + g];
        const float il1 = 1.f / sl[m * 16 + 8 + g];
        float* ob = outp + ((size_t)(b * NS + s) * NT + t0) * NH;
        #pragma unroll
        for (int j = 0; j < 16; j++) {
            *(float2*)&ob[(size_t)(m * 16 + g) * NH + j * 8 + c2] =
                make_float2(acc[j][0] * il0, acc[j][1] * il0);
            *(float2*)&ob[(size_t)(m * 16 + 8 + g) * NH + j * 8 + c2] =
                make_float2(acc[j][2] * il1, acc[j][3] * il1);
        }
    }
}

// ---------------------------------------------------------------------------
extern "C" void kernel_launch(void* const* d_in, const int* in_sizes, int n_in,
                              void* d_out, int out_size) {
    (void)in_sizes; (void)n_in; (void)out_size;
    const float* x   = (const float*)d_in[0];
    const float* adj = (const float*)d_in[1];
    const float* Wq  = (const float*)d_in[2];
    const float* Wk  = (const float*)d_in[3];
    const float* Wv  = (const float*)d_in[4];
    float* out = (float*)d_out;

    cudaFuncSetAttribute(attn_kernel, cudaFuncAttributeMaxDynamicSharedMemorySize,
                         ATTN_SMEM_BYTES);

    qkv_kernel<<<dim3(NB * NT / 64, 1, 1), 256>>>(x, Wq, Wk, Wv);
    scores_kernel<<<dim3(NT / 64, NT / 64, NB), 256>>>();
    attn_kernel<<<dim3(NT / 64, NS, NB), 256, ATTN_SMEM_BYTES>>>(adj, out);
}